// round 1
// baseline (speedup 1.0000x reference)
#include <cuda_runtime.h>

#define Bsz 8
#define Sctx 1024
#define Emb 1024
#define Hn 16
#define DHd 64
#define N3 (3 * Emb)
#define Kdim Emb

#define NEG_MAX 3.402823466e38f

// Scratch: QKV in [3][B][H][S][DH] layout (d contiguous). ~96 MB, zero-init at load.
__device__ float g_qkv[(size_t)3 * Bsz * Hn * Sctx * DHd];
__device__ int g_l[Bsz];

// ---------------------------------------------------------------------------
// Normalize valid-length array: reference declares int64 but JAX without x64
// demotes to int32. Detect on-device: if the second 32-bit word is 0, the
// buffer is little-endian int64 (values are in [1,1024], so the int32 case
// always has word[1] >= 1).
// ---------------------------------------------------------------------------
__global__ void prep_l_kernel(const int* __restrict__ lraw) {
    if (lraw[1] == 0) {
        const long long* l64 = (const long long*)lraw;
        for (int i = 0; i < Bsz; i++) g_l[i] = (int)l64[i];
    } else {
        for (int i = 0; i < Bsz; i++) g_l[i] = lraw[i];
    }
}

// ---------------------------------------------------------------------------
// QKV GEMM: C[m,n] = sum_k x[m,k] * W[n,k] + b[n], scattered into g_qkv.
// 128x128 tile, BK=16, 256 threads, 8x8 microtile. Skips row-tiles where all
// queries are padded (s0 >= l[b]) — those values are never read downstream.
// ---------------------------------------------------------------------------
#define BM 128
#define BN 128
#define BKG 16

__global__ __launch_bounds__(256) void qkv_gemm(const float* __restrict__ x,
                                                const float* __restrict__ W,
                                                const float* __restrict__ bias) {
    __shared__ float As[BKG][BM];
    __shared__ float Bs[BKG][BN];

    int m0 = blockIdx.y * BM;
    int n0 = blockIdx.x * BN;
    int batch = m0 / Sctx;
    int s0 = m0 % Sctx;
    int lb = g_l[batch];
    if (s0 >= lb) return;  // whole tile padded -> never read

    int tid = threadIdx.x;
    int tx = tid % 16;
    int ty = tid / 16;

    float acc[8][8];
#pragma unroll
    for (int i = 0; i < 8; i++)
#pragma unroll
        for (int j = 0; j < 8; j++) acc[i][j] = 0.f;

    for (int k0 = 0; k0 < Kdim; k0 += BKG) {
        // Load A (x) and B (W) tiles, transposed to k-major in smem.
#pragma unroll
        for (int li = 0; li < 2; li++) {
            int idx = tid + li * 256;  // 0..511 over 512 float4
            int r = idx >> 2;          // 0..127
            int q = idx & 3;           // 0..3
            float4 av = *(const float4*)&x[(size_t)(m0 + r) * Kdim + k0 + q * 4];
            As[q * 4 + 0][r] = av.x;
            As[q * 4 + 1][r] = av.y;
            As[q * 4 + 2][r] = av.z;
            As[q * 4 + 3][r] = av.w;
            float4 bv = *(const float4*)&W[(size_t)(n0 + r) * Kdim + k0 + q * 4];
            Bs[q * 4 + 0][r] = bv.x;
            Bs[q * 4 + 1][r] = bv.y;
            Bs[q * 4 + 2][r] = bv.z;
            Bs[q * 4 + 3][r] = bv.w;
        }
        __syncthreads();

#pragma unroll
        for (int kk = 0; kk < BKG; kk++) {
            float a[8], bb[8];
            *(float4*)&a[0] = *(const float4*)&As[kk][ty * 8];
            *(float4*)&a[4] = *(const float4*)&As[kk][ty * 8 + 4];
            *(float4*)&bb[0] = *(const float4*)&Bs[kk][tx * 8];
            *(float4*)&bb[4] = *(const float4*)&Bs[kk][tx * 8 + 4];
#pragma unroll
            for (int i = 0; i < 8; i++)
#pragma unroll
                for (int j = 0; j < 8; j++) acc[i][j] += a[i] * bb[j];
        }
        __syncthreads();
    }

    // Epilogue: add bias, scatter into [3][B][H][S][DH].
#pragma unroll
    for (int j = 0; j < 8; j++) {
        int n = n0 + tx * 8 + j;
        float bv = bias[n];
        int which = n >> 10;          // 0..2
        int h = (n >> 6) & (Hn - 1);  // 0..15
        int d = n & 63;
        size_t base = ((((size_t)which * Bsz + batch) * Hn + h) * Sctx) * DHd + d;
#pragma unroll
        for (int i = 0; i < 8; i++) {
            int s = s0 + ty * 8 + i;
            if (s < lb) g_qkv[base + (size_t)s * DHd] = acc[i][j] + bv;
        }
    }
}

// ---------------------------------------------------------------------------
// Flash attention, fp32. One block per (b, h, 64-query tile). 64-wide key
// tiles, online softmax. Causal + padding: query s valid iff s < l[b]; then
// keys are exactly t <= s. Padded query rows -> exact 0 output.
// ---------------------------------------------------------------------------
#define BQ 64
#define BKT 64
// floats: Qs 4096 | Ks 4096 | Vs 4096 | Ss 64*68 | sc 64 | ls 64
#define ATTN_SMEM_FLOATS (3 * 4096 + 64 * 68 + 128)
#define ATTN_SMEM_BYTES (ATTN_SMEM_FLOATS * 4)

__global__ __launch_bounds__(256) void attn_kernel(float* __restrict__ out) {
    extern __shared__ float sm[];
    float* Qs = sm;                     // [d][i]  (k-major, 64x64)
    float* Ks = sm + 4096;              // [d][j]
    float* Vs = sm + 8192;              // [j][d]
    float* Ss = sm + 12288;             // [i][j]  stride 68 (bank-spread)
    float* sc_s = sm + 12288 + 64 * 68; // per-row rescale
    float* ls_s = sc_s + 64;            // per-row final sum

    int bh = blockIdx.y;
    int b = bh >> 4;
    int h = bh & 15;
    int q0 = blockIdx.x * BQ;
    int lb = g_l[b];
    int tid = threadIdx.x;

    float* outp = out + ((size_t)b * Sctx) * Emb + h * DHd;

    int iA = tid >> 2;   // acc row (0..63)
    int gA = tid & 3;    // d-group (0..3)
    int d0 = gA * 16;

    if (q0 >= lb) {
        // Entire tile padded: output exact zeros.
        float4 z = make_float4(0.f, 0.f, 0.f, 0.f);
#pragma unroll
        for (int q = 0; q < 4; q++)
            *(float4*)&outp[(size_t)(q0 + iA) * Emb + d0 + q * 4] = z;
        return;
    }

    const float* qg = g_qkv + (((size_t)(0 * Bsz + b) * Hn + h) * Sctx) * DHd;
    const float* kg = g_qkv + (((size_t)(1 * Bsz + b) * Hn + h) * Sctx) * DHd;
    const float* vg = g_qkv + (((size_t)(2 * Bsz + b) * Hn + h) * Sctx) * DHd;

    // Load Q tile transposed into smem (d-major).
#pragma unroll
    for (int li = 0; li < 4; li++) {
        int idx = tid + li * 256;  // 0..1023 float4
        int r = idx >> 4;          // row 0..63
        int q = idx & 15;          // d quad
        float4 v = *(const float4*)&qg[(size_t)(q0 + r) * DHd + q * 4];
        Qs[(q * 4 + 0) * 64 + r] = v.x;
        Qs[(q * 4 + 1) * 64 + r] = v.y;
        Qs[(q * 4 + 2) * 64 + r] = v.z;
        Qs[(q * 4 + 3) * 64 + r] = v.w;
    }

    float acc[16];
#pragma unroll
    for (int dd = 0; dd < 16; dd++) acc[dd] = 0.f;
    float m_run = -NEG_MAX;
    float l_run = 0.f;

    int tyS = tid >> 4;  // score rows tyS*4..+3
    int txS = tid & 15;  // score cols txS*4..+3

    int kend = min(lb, q0 + BQ);
    int ntiles = (kend + BKT - 1) / BKT;

    for (int jt = 0; jt < ntiles; jt++) {
        int j0 = jt * BKT;
        __syncthreads();
        // Load K (transposed) and V tiles. Clamp padded V rows to zero
        // (0 * garbage would otherwise be able to poison acc via NaN).
#pragma unroll
        for (int li = 0; li < 4; li++) {
            int idx = tid + li * 256;
            int r = idx >> 4;
            int q = idx & 15;
            float4 kv = *(const float4*)&kg[(size_t)(j0 + r) * DHd + q * 4];
            Ks[(q * 4 + 0) * 64 + r] = kv.x;
            Ks[(q * 4 + 1) * 64 + r] = kv.y;
            Ks[(q * 4 + 2) * 64 + r] = kv.z;
            Ks[(q * 4 + 3) * 64 + r] = kv.w;
            float4 vv = make_float4(0.f, 0.f, 0.f, 0.f);
            if (j0 + r < lb) vv = *(const float4*)&vg[(size_t)(j0 + r) * DHd + q * 4];
            *(float4*)&Vs[r * 64 + q * 4] = vv;
        }
        __syncthreads();

        // Scores: S = Q K^T * (1/sqrt(E)); 4x4 microtile per thread.
        float sacc[4][4];
#pragma unroll
        for (int ii = 0; ii < 4; ii++)
#pragma unroll
            for (int jj = 0; jj < 4; jj++) sacc[ii][jj] = 0.f;
#pragma unroll 8
        for (int kk = 0; kk < 64; kk++) {
            float4 qa = *(const float4*)&Qs[kk * 64 + tyS * 4];
            float4 kb = *(const float4*)&Ks[kk * 64 + txS * 4];
            float qv[4] = {qa.x, qa.y, qa.z, qa.w};
            float kv[4] = {kb.x, kb.y, kb.z, kb.w};
#pragma unroll
            for (int ii = 0; ii < 4; ii++)
#pragma unroll
                for (int jj = 0; jj < 4; jj++) sacc[ii][jj] += qv[ii] * kv[jj];
        }
        const float sm_scale = 0.03125f;  // 1/sqrt(1024)
#pragma unroll
        for (int ii = 0; ii < 4; ii++)
#pragma unroll
            for (int jj = 0; jj < 4; jj++)
                Ss[(tyS * 4 + ii) * 68 + txS * 4 + jj] = sacc[ii][jj] * sm_scale;
        __syncthreads();

        // Online softmax: one thread per query row.
        if (tid < BQ) {
            int row = tid;
            int gq = q0 + row;
            if (gq < lb) {
                int vj = min(BKT, gq + 1 - j0);  // valid keys: t <= gq (< lb since gq < lb)
                if (vj < 0) vj = 0;
                float mt = -NEG_MAX;
                for (int j = 0; j < vj; j++) mt = fmaxf(mt, Ss[row * 68 + j]);
                float mnew = fmaxf(m_run, mt);
                float scale = __expf(m_run - mnew);
                float rs = 0.f;
#pragma unroll 8
                for (int j = 0; j < BKT; j++) {
                    float p = (j < vj) ? __expf(Ss[row * 68 + j] - mnew) : 0.f;
                    Ss[row * 68 + j] = p;
                    rs += p;
                }
                l_run = l_run * scale + rs;
                m_run = mnew;
                sc_s[row] = scale;
            } else {
                sc_s[row] = 1.f;
            }
        }
        __syncthreads();

        // acc = acc * scale + P V
        {
            float scale = sc_s[iA];
#pragma unroll
            for (int dd = 0; dd < 16; dd++) acc[dd] *= scale;
#pragma unroll 8
            for (int j = 0; j < BKT; j++) {
                float p = Ss[iA * 68 + j];
                float4 v0 = *(const float4*)&Vs[j * 64 + d0 + 0];
                float4 v1 = *(const float4*)&Vs[j * 64 + d0 + 4];
                float4 v2 = *(const float4*)&Vs[j * 64 + d0 + 8];
                float4 v3 = *(const float4*)&Vs[j * 64 + d0 + 12];
                acc[0] += p * v0.x;  acc[1] += p * v0.y;
                acc[2] += p * v0.z;  acc[3] += p * v0.w;
                acc[4] += p * v1.x;  acc[5] += p * v1.y;
                acc[6] += p * v1.z;  acc[7] += p * v1.w;
                acc[8] += p * v2.x;  acc[9] += p * v2.y;
                acc[10] += p * v2.z; acc[11] += p * v2.w;
                acc[12] += p * v3.x; acc[13] += p * v3.y;
                acc[14] += p * v3.z; acc[15] += p * v3.w;
            }
        }
    }

    if (tid < BQ) ls_s[tid] = l_run;
    __syncthreads();

    int gq = q0 + iA;
    if (gq < lb) {
        float inv = 1.0f / ls_s[iA];
        float o[16];
#pragma unroll
        for (int dd = 0; dd < 16; dd++) o[dd] = acc[dd] * inv;
#pragma unroll
        for (int q = 0; q < 4; q++)
            *(float4*)&outp[(size_t)gq * Emb + d0 + q * 4] = *(float4*)&o[q * 4];
    } else {
        float4 z = make_float4(0.f, 0.f, 0.f, 0.f);
#pragma unroll
        for (int q = 0; q < 4; q++)
            *(float4*)&outp[(size_t)gq * Emb + d0 + q * 4] = z;
    }
}

// ---------------------------------------------------------------------------

extern "C" void kernel_launch(void* const* d_in, const int* in_sizes, int n_in,
                              void* d_out, int out_size) {
    const float* x = (const float*)d_in[0];
    const int* lraw = (const int*)d_in[1];
    const float* W = (const float*)d_in[2];
    const float* bias = (const float*)d_in[3];
    float* out = (float*)d_out;

    cudaFuncSetAttribute(attn_kernel, cudaFuncAttributeMaxDynamicSharedMemorySize,
                         ATTN_SMEM_BYTES);

    prep_l_kernel<<<1, 1>>>(lraw);

    dim3 ggrid(N3 / BN, (Bsz * Sctx) / BM);
    qkv_gemm<<<ggrid, 256>>>(x, W, bias);

    dim3 agrid(Sctx / BQ, Bsz * Hn);
    attn_kernel<<<agrid, 256, ATTN_SMEM_BYTES>>>(out);
}

// round 4
// speedup vs baseline: 1.6012x; 1.6012x over previous
#include <cuda_runtime.h>
#include <cstdint>

#define Bsz 8
#define Sctx 1024
#define Emb 1024
#define Hn 16
#define DHd 64
#define N3 (3 * Emb)
#define Kdim Emb

#define NEG_MAX 3.402823466e38f

// Scratch: QKV in [3][B][H][S][DH] layout (d contiguous). Zero-init at load;
// rows s >= l[b] are never written, so they stay 0 (finite) forever.
__device__ float g_qkv[(size_t)3 * Bsz * Hn * Sctx * DHd];
__device__ int g_l[Bsz];

__device__ __forceinline__ uint32_t smem_u32(const void* p) {
    uint32_t a;
    asm("{ .reg .u64 t; cvta.to.shared.u64 t, %1; cvt.u32.u64 %0, t; }" : "=r"(a) : "l"(p));
    return a;
}

#define CP_ASYNC16(dst, src) \
    asm volatile("cp.async.cg.shared.global [%0], [%1], 16;" :: "r"(dst), "l"(src))
#define CP_COMMIT() asm volatile("cp.async.commit_group;")
#define CP_WAIT(n) asm volatile("cp.async.wait_group %0;" :: "n"(n))

// mma.sync m16n8k8 tf32: D = A*B + D (fp32 accum). A row-major, B col-major.
__device__ __forceinline__ void mma_tf32(float& c0, float& c1, float& c2, float& c3,
                                         uint32_t a0, uint32_t a1, uint32_t a2, uint32_t a3,
                                         uint32_t b0, uint32_t b1) {
    asm volatile(
        "mma.sync.aligned.m16n8k8.row.col.f32.tf32.tf32.f32 "
        "{%0,%1,%2,%3}, {%4,%5,%6,%7}, {%8,%9}, {%0,%1,%2,%3};"
        : "+f"(c0), "+f"(c1), "+f"(c2), "+f"(c3)
        : "r"(a0), "r"(a1), "r"(a2), "r"(a3), "r"(b0), "r"(b1));
}

// ---------------------------------------------------------------------------
// prep_l: reference declares int64 but JAX w/o x64 demotes to int32. Values in
// [1,1024], so int32 word[1] >= 1 while int64 high word == 0.
// ---------------------------------------------------------------------------
__global__ void prep_l_kernel(const int* __restrict__ lraw) {
    if (lraw[1] == 0) {
        const long long* l64 = (const long long*)lraw;
        for (int i = 0; i < Bsz; i++) g_l[i] = (int)l64[i];
    } else {
        for (int i = 0; i < Bsz; i++) g_l[i] = lraw[i];
    }
}

// ---------------------------------------------------------------------------
// QKV GEMM: C[m,n] = sum_k x[m,k]*W[n,k] + b[n], via mma.sync tf32.
// CTA tile 128x128x32, 8 warps in 2(m) x 4(n), warp tile 64x32.
// 2-stage cp.async pipeline. Smem row stride 36 floats (16B aligned rows,
// conflict-free fragment LDS: (4*group+tig) mod 32 is a permutation).
// ---------------------------------------------------------------------------
#define GBK 32
#define NKT (Kdim / GBK)     // 32
#define SSTR 36              // floats per smem row
#define TILE_FLOATS (128 * SSTR)
#define BUF_FLOATS (2 * TILE_FLOATS)          // A + B for one stage
#define GEMM_SMEM_BYTES (2 * BUF_FLOATS * 4)  // 2 stages = 73728 B

__global__ __launch_bounds__(256, 2) void qkv_gemm_mma(const float* __restrict__ x,
                                                       const float* __restrict__ W,
                                                       const float* __restrict__ bias) {
    extern __shared__ float smem[];

    int m0 = blockIdx.y * 128;
    int n0 = blockIdx.x * 128;
    int batch = m0 >> 10;
    int s0 = m0 & 1023;
    int lb = g_l[batch];
    if (s0 >= lb) return;  // whole row-tile padded; outputs never read

    int tid = threadIdx.x;
    int wid = tid >> 5;
    int lane = tid & 31;
    int group = lane >> 2;   // 0..7
    int tig = lane & 3;      // 0..3
    int wm = wid >> 2;       // 0..1 -> m offset 64*wm
    int wn = wid & 3;        // 0..3 -> n offset 32*wn

    // cp.async indices: each thread loads 4 float4 per tile (A and B).
    int lrow = tid >> 3;       // 0..31 (+32 per iter)
    int lq = tid & 7;          // float4 index within 32-float row

    uint32_t smem_base = smem_u32(smem);

    float d[4][4][4];
#pragma unroll
    for (int i = 0; i < 4; i++)
#pragma unroll
        for (int j = 0; j < 4; j++)
#pragma unroll
            for (int c = 0; c < 4; c++) d[i][j][c] = 0.f;

    // ---- prefetch stage 0 ----
    {
        uint32_t dstA = smem_base + 0;
        uint32_t dstB = smem_base + TILE_FLOATS * 4;
#pragma unroll
        for (int i = 0; i < 4; i++) {
            int r = lrow + i * 32;
            const float* srcA = &x[(size_t)(m0 + r) * Kdim + 0 * GBK + lq * 4];
            CP_ASYNC16(dstA + (r * SSTR + lq * 4) * 4, srcA);
            const float* srcB = &W[(size_t)(n0 + r) * Kdim + 0 * GBK + lq * 4];
            CP_ASYNC16(dstB + (r * SSTR + lq * 4) * 4, srcB);
        }
        CP_COMMIT();
    }

    for (int kt = 0; kt < NKT; kt++) {
        if (kt + 1 < NKT) {
            int buf = (kt + 1) & 1;
            uint32_t dstA = smem_base + buf * BUF_FLOATS * 4;
            uint32_t dstB = dstA + TILE_FLOATS * 4;
#pragma unroll
            for (int i = 0; i < 4; i++) {
                int r = lrow + i * 32;
                const float* srcA = &x[(size_t)(m0 + r) * Kdim + (kt + 1) * GBK + lq * 4];
                CP_ASYNC16(dstA + (r * SSTR + lq * 4) * 4, srcA);
                const float* srcB = &W[(size_t)(n0 + r) * Kdim + (kt + 1) * GBK + lq * 4];
                CP_ASYNC16(dstB + (r * SSTR + lq * 4) * 4, srcB);
            }
            CP_COMMIT();
            CP_WAIT(1);
        } else {
            CP_WAIT(0);
        }
        __syncthreads();

        const float* As = smem + (kt & 1) * BUF_FLOATS;
        const float* Bs = As + TILE_FLOATS;

#pragma unroll
        for (int ks = 0; ks < 4; ks++) {
            int k0 = ks * 8;
            uint32_t a[4][4];
#pragma unroll
            for (int am = 0; am < 4; am++) {
                int mrow = wm * 64 + am * 16 + group;
                const uint32_t* Ap = (const uint32_t*)&As[mrow * SSTR + k0];
                a[am][0] = Ap[tig];
                a[am][2] = Ap[tig + 4];
                const uint32_t* Ap8 = (const uint32_t*)&As[(mrow + 8) * SSTR + k0];
                a[am][1] = Ap8[tig];
                a[am][3] = Ap8[tig + 4];
            }
            uint32_t b[4][2];
#pragma unroll
            for (int an = 0; an < 4; an++) {
                int nrow = wn * 32 + an * 8 + group;
                const uint32_t* Bp = (const uint32_t*)&Bs[nrow * SSTR + k0];
                b[an][0] = Bp[tig];
                b[an][1] = Bp[tig + 4];
            }
#pragma unroll
            for (int am = 0; am < 4; am++)
#pragma unroll
                for (int an = 0; an < 4; an++)
                    mma_tf32(d[am][an][0], d[am][an][1], d[am][an][2], d[am][an][3],
                             a[am][0], a[am][1], a[am][2], a[am][3],
                             b[an][0], b[an][1]);
        }
        __syncthreads();
    }

    // ---- epilogue: bias add + scatter into [3][B][H][S][DH] ----
#pragma unroll
    for (int am = 0; am < 4; am++) {
#pragma unroll
        for (int an = 0; an < 4; an++) {
            int n = n0 + wn * 32 + an * 8 + tig * 2;   // even
            float2 bv = *(const float2*)&bias[n];
            int which = n >> 10;
            int h = (n >> 6) & (Hn - 1);
            int dd = n & 63;
            size_t base = ((((size_t)which * Bsz + batch) * Hn + h) * Sctx) * DHd + dd;

            int mA = s0 + wm * 64 + am * 16 + group;
            if (mA < lb) {
                float2 o = make_float2(d[am][an][0] + bv.x, d[am][an][1] + bv.y);
                *(float2*)&g_qkv[base + (size_t)mA * DHd] = o;
            }
            int mB = mA + 8;
            if (mB < lb) {
                float2 o = make_float2(d[am][an][2] + bv.x, d[am][an][3] + bv.y);
                *(float2*)&g_qkv[base + (size_t)mB * DHd] = o;
            }
        }
    }
}

// ---------------------------------------------------------------------------
// Flash attention, fp32 (unchanged, known-good). One block per (b,h,64-q tile).
// ---------------------------------------------------------------------------
#define BQ 64
#define BKT 64
#define ATTN_SMEM_FLOATS (3 * 4096 + 64 * 68 + 128)
#define ATTN_SMEM_BYTES (ATTN_SMEM_FLOATS * 4)

__global__ __launch_bounds__(256) void attn_kernel(float* __restrict__ out) {
    extern __shared__ float sm[];
    float* Qs = sm;
    float* Ks = sm + 4096;
    float* Vs = sm + 8192;
    float* Ss = sm + 12288;
    float* sc_s = sm + 12288 + 64 * 68;
    float* ls_s = sc_s + 64;

    int bh = blockIdx.y;
    int b = bh >> 4;
    int h = bh & 15;
    int q0 = blockIdx.x * BQ;
    int lb = g_l[b];
    int tid = threadIdx.x;

    float* outp = out + ((size_t)b * Sctx) * Emb + h * DHd;

    int iA = tid >> 2;
    int gA = tid & 3;
    int d0 = gA * 16;

    if (q0 >= lb) {
        float4 z = make_float4(0.f, 0.f, 0.f, 0.f);
#pragma unroll
        for (int q = 0; q < 4; q++)
            *(float4*)&outp[(size_t)(q0 + iA) * Emb + d0 + q * 4] = z;
        return;
    }

    const float* qg = g_qkv + (((size_t)(0 * Bsz + b) * Hn + h) * Sctx) * DHd;
    const float* kg = g_qkv + (((size_t)(1 * Bsz + b) * Hn + h) * Sctx) * DHd;
    const float* vg = g_qkv + (((size_t)(2 * Bsz + b) * Hn + h) * Sctx) * DHd;

#pragma unroll
    for (int li = 0; li < 4; li++) {
        int idx = tid + li * 256;
        int r = idx >> 4;
        int q = idx & 15;
        float4 v = *(const float4*)&qg[(size_t)(q0 + r) * DHd + q * 4];
        Qs[(q * 4 + 0) * 64 + r] = v.x;
        Qs[(q * 4 + 1) * 64 + r] = v.y;
        Qs[(q * 4 + 2) * 64 + r] = v.z;
        Qs[(q * 4 + 3) * 64 + r] = v.w;
    }

    float acc[16];
#pragma unroll
    for (int dd = 0; dd < 16; dd++) acc[dd] = 0.f;
    float m_run = -NEG_MAX;
    float l_run = 0.f;

    int tyS = tid >> 4;
    int txS = tid & 15;

    int kend = min(lb, q0 + BQ);
    int ntiles = (kend + BKT - 1) / BKT;

    for (int jt = 0; jt < ntiles; jt++) {
        int j0 = jt * BKT;
        __syncthreads();
#pragma unroll
        for (int li = 0; li < 4; li++) {
            int idx = tid + li * 256;
            int r = idx >> 4;
            int q = idx & 15;
            float4 kv = *(const float4*)&kg[(size_t)(j0 + r) * DHd + q * 4];
            Ks[(q * 4 + 0) * 64 + r] = kv.x;
            Ks[(q * 4 + 1) * 64 + r] = kv.y;
            Ks[(q * 4 + 2) * 64 + r] = kv.z;
            Ks[(q * 4 + 3) * 64 + r] = kv.w;
            float4 vv = make_float4(0.f, 0.f, 0.f, 0.f);
            if (j0 + r < lb) vv = *(const float4*)&vg[(size_t)(j0 + r) * DHd + q * 4];
            *(float4*)&Vs[r * 64 + q * 4] = vv;
        }
        __syncthreads();

        float sacc[4][4];
#pragma unroll
        for (int ii = 0; ii < 4; ii++)
#pragma unroll
            for (int jj = 0; jj < 4; jj++) sacc[ii][jj] = 0.f;
#pragma unroll 8
        for (int kk = 0; kk < 64; kk++) {
            float4 qa = *(const float4*)&Qs[kk * 64 + tyS * 4];
            float4 kb = *(const float4*)&Ks[kk * 64 + txS * 4];
            float qv[4] = {qa.x, qa.y, qa.z, qa.w};
            float kv[4] = {kb.x, kb.y, kb.z, kb.w};
#pragma unroll
            for (int ii = 0; ii < 4; ii++)
#pragma unroll
                for (int jj = 0; jj < 4; jj++) sacc[ii][jj] += qv[ii] * kv[jj];
        }
        const float sm_scale = 0.03125f;
#pragma unroll
        for (int ii = 0; ii < 4; ii++)
#pragma unroll
            for (int jj = 0; jj < 4; jj++)
                Ss[(tyS * 4 + ii) * 68 + txS * 4 + jj] = sacc[ii][jj] * sm_scale;
        __syncthreads();

        if (tid < BQ) {
            int row = tid;
            int gq = q0 + row;
            if (gq < lb) {
                int vj = min(BKT, gq + 1 - j0);
                if (vj < 0) vj = 0;
                float mt = -NEG_MAX;
                for (int j = 0; j < vj; j++) mt = fmaxf(mt, Ss[row * 68 + j]);
                float mnew = fmaxf(m_run, mt);
                float scale = __expf(m_run - mnew);
                float rs = 0.f;
#pragma unroll 8
                for (int j = 0; j < BKT; j++) {
                    float p = (j < vj) ? __expf(Ss[row * 68 + j] - mnew) : 0.f;
                    Ss[row * 68 + j] = p;
                    rs += p;
                }
                l_run = l_run * scale + rs;
                m_run = mnew;
                sc_s[row] = scale;
            } else {
                sc_s[row] = 1.f;
            }
        }
        __syncthreads();

        {
            float scale = sc_s[iA];
#pragma unroll
            for (int dd = 0; dd < 16; dd++) acc[dd] *= scale;
#pragma unroll 8
            for (int j = 0; j < BKT; j++) {
                float p = Ss[iA * 68 + j];
                float4 v0 = *(const float4*)&Vs[j * 64 + d0 + 0];
                float4 v1 = *(const float4*)&Vs[j * 64 + d0 + 4];
                float4 v2 = *(const float4*)&Vs[j * 64 + d0 + 8];
                float4 v3 = *(const float4*)&Vs[j * 64 + d0 + 12];
                acc[0] += p * v0.x;  acc[1] += p * v0.y;
                acc[2] += p * v0.z;  acc[3] += p * v0.w;
                acc[4] += p * v1.x;  acc[5] += p * v1.y;
                acc[6] += p * v1.z;  acc[7] += p * v1.w;
                acc[8] += p * v2.x;  acc[9] += p * v2.y;
                acc[10] += p * v2.z; acc[11] += p * v2.w;
                acc[12] += p * v3.x; acc[13] += p * v3.y;
                acc[14] += p * v3.z; acc[15] += p * v3.w;
            }
        }
    }

    if (tid < BQ) ls_s[tid] = l_run;
    __syncthreads();

    int gq = q0 + iA;
    if (gq < lb) {
        float inv = 1.0f / ls_s[iA];
        float o[16];
#pragma unroll
        for (int dd = 0; dd < 16; dd++) o[dd] = acc[dd] * inv;
#pragma unroll
        for (int q = 0; q < 4; q++)
            *(float4*)&outp[(size_t)gq * Emb + d0 + q * 4] = *(float4*)&o[q * 4];
    } else {
        float4 z = make_float4(0.f, 0.f, 0.f, 0.f);
#pragma unroll
        for (int q = 0; q < 4; q++)
            *(float4*)&outp[(size_t)gq * Emb + d0 + q * 4] = z;
    }
}

// ---------------------------------------------------------------------------

extern "C" void kernel_launch(void* const* d_in, const int* in_sizes, int n_in,
                              void* d_out, int out_size) {
    const float* x = (const float*)d_in[0];
    const int* lraw = (const int*)d_in[1];
    const float* W = (const float*)d_in[2];
    const float* bias = (const float*)d_in[3];
    float* out = (float*)d_out;

    cudaFuncSetAttribute(qkv_gemm_mma, cudaFuncAttributeMaxDynamicSharedMemorySize,
                         GEMM_SMEM_BYTES);
    cudaFuncSetAttribute(attn_kernel, cudaFuncAttributeMaxDynamicSharedMemorySize,
                         ATTN_SMEM_BYTES);

    prep_l_kernel<<<1, 1>>>(lraw);

    dim3 ggrid(N3 / 128, (Bsz * Sctx) / 128);
    qkv_gemm_mma<<<ggrid, 256, GEMM_SMEM_BYTES>>>(x, W, bias);

    dim3 agrid(Sctx / BQ, Bsz * Hn);
    attn_kernel<<<agrid, 256, ATTN_SMEM_BYTES>>>(out);
}